// round 12
// baseline (speedup 1.0000x reference)
#include <cuda_runtime.h>
#include <math.h>
#include <stdint.h>

// Problem constants (fixed by the dataset)
#define NB        16384
#define BDIM      (3 * NB)        // 49152 floats per row
#define BDIM_F4   (BDIM / 4)      // 12288 float4 per row
#define BATCH     4096

#define THREADS       256
#define ROWS_PT       8                           // rows accumulated per thread
#define CHUNKS        6                           // column chunks per CTA tile
#define F4_PER_TILE   (THREADS * CHUNKS)          // 1536 float4
#define COL_TILES     (BDIM_F4 / F4_PER_TILE)     // 8
#define ROW_GROUPS    (BATCH / ROWS_PT)           // 512
#define GRIDX         38                          // 38*8 = 304 = 2 CTAs/SM * 152 SMs

// Transposed weights: g_WT[j*3 + k] = W(j/3)[k][j%3]  (j = x column)
__device__ float g_WT[BDIM * 3];

__device__ __forceinline__ float softplus_f(float v) {
    return (v > 20.0f) ? v : log1pf(expf(v));
}

// Builds transposed W AND zeroes the (poisoned) output buffer.
__global__ void build_w_kernel(const float* __restrict__ w, float* __restrict__ out,
                               int out_n) {
    int n = blockIdx.x * blockDim.x + threadIdx.x;
    if (n < out_n) out[n] = 0.0f;
    if (n >= NB) return;
    float w0 = w[n * 6 + 0], w1 = w[n * 6 + 1], w2 = w[n * 6 + 2];
    float w3 = w[n * 6 + 3], w4 = w[n * 6 + 4], w5 = w[n * 6 + 5];

    float a = softplus_f(w0);
    float b = w1, c = w2;
    float d = softplus_f(w3);
    float e = w4;
    float f = softplus_f(w5);

    float W00 = a * a;
    float W01 = a * b;
    float W02 = a * c;
    float W11 = b * b + d * d;
    float W12 = b * c + d * e;
    float W22 = c * c + e * e + f * f;

    float* p = g_WT + (size_t)n * 9;
    p[0] = W00; p[1] = W01; p[2] = W02;   // x-col 3n
    p[3] = W01; p[4] = W11; p[5] = W12;   // x-col 3n+1
    p[6] = W02; p[7] = W12; p[8] = W22;   // x-col 3n+2
}

// streaming (evict-first) float4 load: x is touched once; keeps W L1-resident.
__device__ __forceinline__ float4 ldcs4(const float4* p) {
    float4 v;
    asm volatile("ld.global.cs.v4.f32 {%0,%1,%2,%3}, [%4];"
                 : "=f"(v.x), "=f"(v.y), "=f"(v.z), "=f"(v.w) : "l"(p));
    return v;
}

__global__ void __launch_bounds__(THREADS, 2)
main_kernel(const float* __restrict__ x, float* __restrict__ out) {
    const int t    = threadIdx.x;
    const int lane = t & 31;
    // y-dim = column tile (all concurrent CTAs of a tile share one 73KB W
    // slice -> L1-resident). x-dim = persistent slot over row-groups.
    const int tile = blockIdx.y;

    const float4* x4 = reinterpret_cast<const float4*>(x);
    const float4* wp = reinterpret_cast<const float4*>(g_WT);

    const int gbase = tile * F4_PER_TILE + t;

    float acc[ROWS_PT * 3];
    #pragma unroll
    for (int i = 0; i < ROWS_PT * 3; ++i) acc[i] = 0.0f;

    // Double-buffered 8-load batches, pipelined ACROSS unit boundaries so the
    // end-of-unit reduce runs under outstanding loads.
    float4 xb[2][ROWS_PT];

    auto load_batch = [&](int p, int rg, int c) {
        const float4* xp = x4 + (size_t)(rg * ROWS_PT) * BDIM_F4
                              + (gbase + c * THREADS);
        #pragma unroll
        for (int r = 0; r < ROWS_PT; ++r)
            xb[p][r] = ldcs4(xp + (size_t)r * BDIM_F4);
    };

    auto compute = [&](int p, int c) {
        const int g = gbase + c * THREADS;
        float4 w0 = __ldg(wp + 3 * g + 0);   // L1 hits after first unit
        float4 w1 = __ldg(wp + 3 * g + 1);
        float4 w2 = __ldg(wp + 3 * g + 2);
        float wf[12] = { w0.x, w0.y, w0.z, w0.w,
                         w1.x, w1.y, w1.z, w1.w,
                         w2.x, w2.y, w2.z, w2.w };
        #pragma unroll
        for (int r = 0; r < ROWS_PT; ++r) {
            float xc[4] = { xb[p][r].x, xb[p][r].y, xb[p][r].z, xb[p][r].w };
            #pragma unroll
            for (int cc = 0; cc < 4; ++cc) {
                acc[r * 3 + 0] = fmaf(wf[cc * 3 + 0], xc[cc], acc[r * 3 + 0]);
                acc[r * 3 + 1] = fmaf(wf[cc * 3 + 1], xc[cc], acc[r * 3 + 1]);
                acc[r * 3 + 2] = fmaf(wf[cc * 3 + 2], xc[cc], acc[r * 3 + 2]);
            }
        }
    };

    int pb = 0;
    load_batch(0, blockIdx.x, 0);

    for (int rg = blockIdx.x; rg < ROW_GROUPS; rg += GRIDX) {
        #pragma unroll
        for (int c = 0; c < CHUNKS; ++c) {
            // prefetch the next work item (possibly next unit's chunk 0)
            int nc = c + 1, nrg = rg;
            if (nc == CHUNKS) { nc = 0; nrg = rg + GRIDX; }
            if (nrg < ROW_GROUPS) load_batch(pb ^ 1, nrg, nc);
            compute(pb, c);
            pb ^= 1;
        }

        // reduce + atomics for this unit; next unit's batch-0 is in flight
        #pragma unroll
        for (int off = 16; off; off >>= 1) {
            #pragma unroll
            for (int i = 0; i < ROWS_PT * 3; ++i)
                acc[i] += __shfl_down_sync(0xffffffffu, acc[i], off);
        }
        if (lane == 0) {
            const int row0 = rg * ROWS_PT;
            #pragma unroll
            for (int r = 0; r < ROWS_PT; ++r) {
                atomicAdd(&out[(row0 + r) * 3 + 0], acc[r * 3 + 0]);
                atomicAdd(&out[(row0 + r) * 3 + 1], acc[r * 3 + 1]);
                atomicAdd(&out[(row0 + r) * 3 + 2], acc[r * 3 + 2]);
            }
        }
        #pragma unroll
        for (int i = 0; i < ROWS_PT * 3; ++i) acc[i] = 0.0f;
    }
}

extern "C" void kernel_launch(void* const* d_in, const int* in_sizes, int n_in,
                              void* d_out, int out_size) {
    const float* x      = (const float*)d_in[0];   // [4096, 49152] f32
    const float* weight = (const float*)d_in[1];   // [16384, 6]    f32
    float* out          = (float*)d_out;           // [4096, 3]     f32

    // 1) build transposed W + zero the poisoned output (atomics accumulate)
    build_w_kernel<<<(NB + 255) / 256, 256>>>(weight, out, out_size);

    // 2) persistent, cross-unit pipelined streaming reduction
    dim3 grid(GRIDX, COL_TILES);
    main_kernel<<<grid, THREADS>>>(x, out);
}

// round 13
// speedup vs baseline: 1.1042x; 1.1042x over previous
#include <cuda_runtime.h>
#include <math.h>
#include <stdint.h>

// Problem constants (fixed by the dataset)
#define NB        16384
#define BDIM      (3 * NB)        // 49152 floats per row
#define BDIM_F4   (BDIM / 4)      // 12288 float4 per row
#define BATCH     4096

#define THREADS       256
#define ROWS_PT       8                           // rows accumulated per thread
#define CHUNKS        12                          // column chunks per CTA (even!)
#define F4_PER_TILE   (THREADS * CHUNKS)          // 3072 float4
#define COL_TILES     (BDIM_F4 / F4_PER_TILE)     // 4
#define ROW_GROUPS    (BATCH / ROWS_PT)           // 512

// Transposed weights: g_WT[j*3 + k] = W(j/3)[k][j%3]  (j = x column)
__device__ float g_WT[BDIM * 3];

__device__ __forceinline__ float softplus_f(float v) {
    return (v > 20.0f) ? v : log1pf(expf(v));
}

// Builds transposed W AND zeroes the (poisoned) output buffer.
__global__ void build_w_kernel(const float* __restrict__ w, float* __restrict__ out,
                               int out_n) {
    int n = blockIdx.x * blockDim.x + threadIdx.x;
    if (n < out_n) out[n] = 0.0f;
    if (n >= NB) return;
    float w0 = w[n * 6 + 0], w1 = w[n * 6 + 1], w2 = w[n * 6 + 2];
    float w3 = w[n * 6 + 3], w4 = w[n * 6 + 4], w5 = w[n * 6 + 5];

    float a = softplus_f(w0);
    float b = w1, c = w2;
    float d = softplus_f(w3);
    float e = w4;
    float f = softplus_f(w5);

    float W00 = a * a;
    float W01 = a * b;
    float W02 = a * c;
    float W11 = b * b + d * d;
    float W12 = b * c + d * e;
    float W22 = c * c + e * e + f * f;

    float* p = g_WT + (size_t)n * 9;
    p[0] = W00; p[1] = W01; p[2] = W02;   // x-col 3n
    p[3] = W01; p[4] = W11; p[5] = W12;   // x-col 3n+1
    p[6] = W02; p[7] = W12; p[8] = W22;   // x-col 3n+2
}

// streaming (evict-first) float4 load: x is touched once; keeps W L1-resident.
__device__ __forceinline__ float4 ldcs4(const float4* p) {
    float4 v;
    asm volatile("ld.global.cs.v4.f32 {%0,%1,%2,%3}, [%4];"
                 : "=f"(v.x), "=f"(v.y), "=f"(v.z), "=f"(v.w) : "l"(p));
    return v;
}

__global__ void __launch_bounds__(THREADS, 2)
main_kernel(const float* __restrict__ x, float* __restrict__ out) {
    const int t    = threadIdx.x;
    const int lane = t & 31;
    // Grid: x-dim = row-group (fast), y-dim = column tile (slow) ->
    // all concurrent CTAs share one 147KB W slice (L1-resident, ldcs-protected).
    const int tile = blockIdx.y;
    const int row0 = blockIdx.x * ROWS_PT;

    const float4* x4 = reinterpret_cast<const float4*>(x);
    const float4* wp = reinterpret_cast<const float4*>(g_WT);

    float acc[ROWS_PT * 3];
    #pragma unroll
    for (int i = 0; i < ROWS_PT * 3; ++i) acc[i] = 0.0f;

    const int gbase = tile * F4_PER_TILE + t;
    const float4* xrow = x4 + (size_t)row0 * BDIM_F4;

    // Two alternating 8-load batches: while computing batch p, batch p^1 is in flight.
    float4 xb[2][ROWS_PT];

    auto load_batch = [&](int p, int c) {
        const float4* xp = xrow + (gbase + c * THREADS);
        #pragma unroll
        for (int r = 0; r < ROWS_PT; ++r)
            xb[p][r] = ldcs4(xp + (size_t)r * BDIM_F4);
    };

    auto compute = [&](int p, int c) {
        const int g = gbase + c * THREADS;
        float4 w0 = __ldg(wp + 3 * g + 0);   // L1 hits after first CTA on SM
        float4 w1 = __ldg(wp + 3 * g + 1);
        float4 w2 = __ldg(wp + 3 * g + 2);
        float wf[12] = { w0.x, w0.y, w0.z, w0.w,
                         w1.x, w1.y, w1.z, w1.w,
                         w2.x, w2.y, w2.z, w2.w };
        #pragma unroll
        for (int r = 0; r < ROWS_PT; ++r) {
            float xc[4] = { xb[p][r].x, xb[p][r].y, xb[p][r].z, xb[p][r].w };
            #pragma unroll
            for (int cc = 0; cc < 4; ++cc) {
                acc[r * 3 + 0] = fmaf(wf[cc * 3 + 0], xc[cc], acc[r * 3 + 0]);
                acc[r * 3 + 1] = fmaf(wf[cc * 3 + 1], xc[cc], acc[r * 3 + 1]);
                acc[r * 3 + 2] = fmaf(wf[cc * 3 + 2], xc[cc], acc[r * 3 + 2]);
            }
        }
    };

    load_batch(0, 0);
    #pragma unroll
    for (int c = 0; c < CHUNKS; ++c) {
        if (c + 1 < CHUNKS) load_batch((c + 1) & 1, c + 1);  // prefetch next
        compute(c & 1, c);
    }

    // One warp tree-reduce (off the streaming path), now amortized over 2x bytes
    #pragma unroll
    for (int off = 16; off; off >>= 1) {
        #pragma unroll
        for (int i = 0; i < ROWS_PT * 3; ++i)
            acc[i] += __shfl_down_sync(0xffffffffu, acc[i], off);
    }
    if (lane == 0) {
        #pragma unroll
        for (int r = 0; r < ROWS_PT; ++r) {
            atomicAdd(&out[(row0 + r) * 3 + 0], acc[r * 3 + 0]);
            atomicAdd(&out[(row0 + r) * 3 + 1], acc[r * 3 + 1]);
            atomicAdd(&out[(row0 + r) * 3 + 2], acc[r * 3 + 2]);
        }
    }
}

extern "C" void kernel_launch(void* const* d_in, const int* in_sizes, int n_in,
                              void* d_out, int out_size) {
    const float* x      = (const float*)d_in[0];   // [4096, 49152] f32
    const float* weight = (const float*)d_in[1];   // [16384, 6]    f32
    float* out          = (float*)d_out;           // [4096, 3]     f32

    // 1) build transposed W + zero the poisoned output (atomics accumulate)
    build_w_kernel<<<(NB + 255) / 256, 256>>>(weight, out, out_size);

    // 2) software-pipelined streaming reduction, coarser CTAs (fewer reduce bubbles)
    dim3 grid(ROW_GROUPS, COL_TILES);
    main_kernel<<<grid, THREADS>>>(x, out);
}